// round 1
// baseline (speedup 1.0000x reference)
#include <cuda_runtime.h>
#include <math.h>

// Problem constants
#define BTOK 4096      // B*N tokens
#define CDIM 1024      // model dim
#define H3   3072      // 3*C
#define HID  4096      // FFN hidden
#define NSEQ 2048
#define NHEAD 16
#define HD   64

// Scratch (static device globals; no allocation in kernel_launch)
__device__ float g_xn[BTOK * CDIM];    // layernorm output (reused for ln1 and ln2)
__device__ float g_qkv[BTOK * H3];     // qkv projections
__device__ float g_att[BTOK * CDIM];   // attention output (b,n,h,hd)
__device__ float g_h[BTOK * HID];      // gelu(fc1) output

// ---------------------------------------------------------------------------
// LayerNorm: one row (1024 floats) per block, 256 threads, float4 vectorized
// ---------------------------------------------------------------------------
__global__ __launch_bounds__(256)
void ln_kernel(const float* __restrict__ x, const float* __restrict__ gg,
               const float* __restrict__ bb, float* __restrict__ y) {
    __shared__ float red0[8], red1[8];
    __shared__ float s_mu, s_rs;
    int row = blockIdx.x;
    int tid = threadIdx.x;
    const float4* xr = (const float4*)(x + (size_t)row * CDIM);
    float4 v = xr[tid];
    float s  = v.x + v.y + v.z + v.w;
    float s2 = v.x * v.x + v.y * v.y + v.z * v.z + v.w * v.w;
    #pragma unroll
    for (int o = 16; o; o >>= 1) {
        s  += __shfl_xor_sync(0xFFFFFFFFu, s,  o);
        s2 += __shfl_xor_sync(0xFFFFFFFFu, s2, o);
    }
    if ((tid & 31) == 0) { red0[tid >> 5] = s; red1[tid >> 5] = s2; }
    __syncthreads();
    if (tid == 0) {
        float a = 0.f, b2 = 0.f;
        #pragma unroll
        for (int i = 0; i < 8; i++) { a += red0[i]; b2 += red1[i]; }
        float mu  = a * (1.0f / CDIM);
        float var = b2 * (1.0f / CDIM) - mu * mu;
        s_mu = mu;
        s_rs = rsqrtf(var + 1e-5f);
    }
    __syncthreads();
    float mu = s_mu, rs = s_rs;
    float4 gv = ((const float4*)gg)[tid];
    float4 bv = ((const float4*)bb)[tid];
    float4 o;
    o.x = (v.x - mu) * rs * gv.x + bv.x;
    o.y = (v.y - mu) * rs * gv.y + bv.y;
    o.z = (v.z - mu) * rs * gv.z + bv.z;
    o.w = (v.w - mu) * rs * gv.w + bv.w;
    ((float4*)(y + (size_t)row * CDIM))[tid] = o;
}

// ---------------------------------------------------------------------------
// SGEMM: C[m,n] = sum_k A[m,k] * B[n,k]  (A: MxK row-major, B: NxK row-major)
// 128x128 block tile, BK=8, 256 threads, 8x8 per thread.
// EPI: 0 = plain; 2 = gelu(dot + bias); 3 = res + dot + bias
// ---------------------------------------------------------------------------
template <int EPI>
__global__ __launch_bounds__(256)
void sgemm(const float* __restrict__ A, const float* __restrict__ B,
           const float* __restrict__ bias, const float* __restrict__ res,
           float* __restrict__ Cout, int M, int N, int K) {
    __shared__ float As[8][132];
    __shared__ float Bs[8][132];
    int tid = threadIdx.x;
    int m0 = blockIdx.y * 128;
    int n0 = blockIdx.x * 128;
    int lr = tid >> 1;          // 0..127 (tile row to load)
    int lk = (tid & 1) * 4;     // 0 or 4 (k sub-offset)
    const float* Ag = A + (size_t)(m0 + lr) * K + lk;
    const float* Bg = B + (size_t)(n0 + lr) * K + lk;
    int tx = tid & 15, ty = tid >> 4;

    float acc[8][8];
    #pragma unroll
    for (int i = 0; i < 8; i++)
        #pragma unroll
        for (int j = 0; j < 8; j++) acc[i][j] = 0.f;

    for (int k0 = 0; k0 < K; k0 += 8) {
        float4 av = *(const float4*)(Ag + k0);
        float4 bv = *(const float4*)(Bg + k0);
        __syncthreads();
        As[lk + 0][lr] = av.x; As[lk + 1][lr] = av.y;
        As[lk + 2][lr] = av.z; As[lk + 3][lr] = av.w;
        Bs[lk + 0][lr] = bv.x; Bs[lk + 1][lr] = bv.y;
        Bs[lk + 2][lr] = bv.z; Bs[lk + 3][lr] = bv.w;
        __syncthreads();
        #pragma unroll
        for (int kk = 0; kk < 8; kk++) {
            float4 a0 = *(const float4*)&As[kk][ty * 4];
            float4 a1 = *(const float4*)&As[kk][64 + ty * 4];
            float4 b0 = *(const float4*)&Bs[kk][tx * 4];
            float4 b1 = *(const float4*)&Bs[kk][64 + tx * 4];
            float af[8] = {a0.x, a0.y, a0.z, a0.w, a1.x, a1.y, a1.z, a1.w};
            float bf[8] = {b0.x, b0.y, b0.z, b0.w, b1.x, b1.y, b1.z, b1.w};
            #pragma unroll
            for (int i = 0; i < 8; i++)
                #pragma unroll
                for (int j = 0; j < 8; j++)
                    acc[i][j] += af[i] * bf[j];
        }
    }

    #pragma unroll
    for (int i = 0; i < 8; i++) {
        int row = m0 + ((i < 4) ? (ty * 4 + i) : (64 + ty * 4 + (i - 4)));
        #pragma unroll
        for (int jh = 0; jh < 2; jh++) {
            int col = n0 + jh * 64 + tx * 4;
            float4 o;
            float* op = (float*)&o;
            #pragma unroll
            for (int j = 0; j < 4; j++) {
                float v = acc[i][jh * 4 + j];
                if (EPI >= 2) v += __ldg(&bias[col + j]);
                if (EPI == 2) v = 0.5f * v * (1.0f + erff(v * 0.70710678118654752f));
                if (EPI == 3) v += res[(size_t)row * N + col + j];
                op[j] = v;
            }
            *(float4*)(Cout + (size_t)row * N + col) = o;
        }
    }
}

// ---------------------------------------------------------------------------
// Flash-style attention: one q row per thread, 64 q rows per block.
// qkv layout per token: [3, 16 heads, 64] -> q@0, k@1024, v@2048; head h @ h*64.
// Output layout: [b, n, h*64+d] contiguous (ready for proj GEMM).
// ---------------------------------------------------------------------------
__global__ __launch_bounds__(64)
void attn_kernel(const float* __restrict__ qkv, float* __restrict__ out) {
    __shared__ float Ks[64][64];
    __shared__ float Vs[64][64];
    int tid = threadIdx.x;
    int bh = blockIdx.y;
    int b = bh >> 4;
    int h = bh & 15;
    int q0 = blockIdx.x * 64;

    size_t qbase = ((size_t)(b * NSEQ + q0 + tid)) * H3 + h * HD;
    float q[64];
    #pragma unroll
    for (int i = 0; i < 16; i++) {
        float4 v = *(const float4*)(qkv + qbase + i * 4);
        q[4 * i] = v.x; q[4 * i + 1] = v.y; q[4 * i + 2] = v.z; q[4 * i + 3] = v.w;
    }

    float m = -1e30f, l = 0.f;
    float acc[64];
    #pragma unroll
    for (int d = 0; d < 64; d++) acc[d] = 0.f;

    for (int kt = 0; kt < NSEQ; kt += 64) {
        __syncthreads();
        #pragma unroll
        for (int it = 0; it < 16; it++) {
            int idx = tid + it * 64;       // 0..1023
            int r = idx >> 4, c4 = idx & 15;
            size_t kb = ((size_t)(b * NSEQ + kt + r)) * H3 + CDIM + h * HD;
            *(float4*)&Ks[r][c4 * 4] = *(const float4*)(qkv + kb + c4 * 4);
            *(float4*)&Vs[r][c4 * 4] = *(const float4*)(qkv + kb + CDIM + c4 * 4);
        }
        __syncthreads();
        #pragma unroll 2
        for (int j = 0; j < 64; j++) {
            float s = 0.f;
            #pragma unroll
            for (int d = 0; d < 64; d++) s += q[d] * Ks[j][d];
            s *= 0.125f;   // 1/sqrt(64)
            if (s > m) {
                float cs = __expf(m - s);
                l *= cs;
                #pragma unroll
                for (int d = 0; d < 64; d++) acc[d] *= cs;
                m = s;
            }
            float p = __expf(s - m);
            l += p;
            #pragma unroll
            for (int d = 0; d < 64; d++) acc[d] += p * Vs[j][d];
        }
    }

    float inv = 1.0f / l;
    size_t ob = ((size_t)(b * NSEQ + q0 + tid)) * CDIM + h * HD;
    #pragma unroll
    for (int i = 0; i < 16; i++) {
        float4 v;
        v.x = acc[4 * i] * inv;     v.y = acc[4 * i + 1] * inv;
        v.z = acc[4 * i + 2] * inv; v.w = acc[4 * i + 3] * inv;
        *(float4*)(out + ob + i * 4) = v;
    }
}

// ---------------------------------------------------------------------------
// Launch sequence
// ---------------------------------------------------------------------------
extern "C" void kernel_launch(void* const* d_in, const int* in_sizes, int n_in,
                              void* d_out, int out_size) {
    const float* x      = (const float*)d_in[0];
    const float* w_qkv  = (const float*)d_in[1];
    const float* w_proj = (const float*)d_in[2];
    const float* b_proj = (const float*)d_in[3];
    const float* ln1_g  = (const float*)d_in[4];
    const float* ln1_b  = (const float*)d_in[5];
    const float* ln2_g  = (const float*)d_in[6];
    const float* ln2_b  = (const float*)d_in[7];
    const float* w_fc1  = (const float*)d_in[8];
    const float* b_fc1  = (const float*)d_in[9];
    const float* w_fc2  = (const float*)d_in[10];
    const float* b_fc2  = (const float*)d_in[11];
    float* out = (float*)d_out;

    float *xn, *qkv, *att, *hbuf;
    cudaGetSymbolAddress((void**)&xn,   g_xn);
    cudaGetSymbolAddress((void**)&qkv,  g_qkv);
    cudaGetSymbolAddress((void**)&att,  g_att);
    cudaGetSymbolAddress((void**)&hbuf, g_h);

    // 1. ln1(x) -> xn
    ln_kernel<<<BTOK, 256>>>(x, ln1_g, ln1_b, xn);
    // 2. qkv = xn @ w_qkv^T          [4096 x 3072]
    sgemm<0><<<dim3(H3 / 128, BTOK / 128), 256>>>(xn, w_qkv, nullptr, nullptr, qkv, BTOK, H3, CDIM);
    // 3. attention                   [4096 x 1024]
    attn_kernel<<<dim3(NSEQ / 64, 2 * NHEAD), 64>>>(qkv, att);
    // 4. x1 = x + att @ w_proj^T + b_proj   -> d_out
    sgemm<3><<<dim3(CDIM / 128, BTOK / 128), 256>>>(att, w_proj, b_proj, x, out, BTOK, CDIM, CDIM);
    // 5. ln2(x1) -> xn
    ln_kernel<<<BTOK, 256>>>(out, ln2_g, ln2_b, xn);
    // 6. h = gelu(xn @ w_fc1^T + b_fc1)     [4096 x 4096]
    sgemm<2><<<dim3(HID / 128, BTOK / 128), 256>>>(xn, w_fc1, b_fc1, nullptr, hbuf, BTOK, HID, CDIM);
    // 7. out = x1 + h @ w_fc2^T + b_fc2 (in-place residual from d_out)
    sgemm<3><<<dim3(CDIM / 128, BTOK / 128), 256>>>(hbuf, w_fc2, b_fc2, out, out, BTOK, CDIM, HID);
}

// round 3
// speedup vs baseline: 2.2291x; 2.2291x over previous
#include <cuda_runtime.h>
#include <cuda_fp16.h>
#include <math.h>
#include <stdint.h>

// Problem constants
#define BTOK 4096      // B*N tokens
#define CDIM 1024      // model dim
#define H3   3072      // 3*C
#define HID  4096      // FFN hidden
#define NSEQ 2048
#define NHEAD 16
#define HD   64

// Scratch buffers (device globals; no allocation in kernel_launch)
__device__ float  g_qkv[BTOK * H3];       // qkv projections (fp32, read by attention)
__device__ __half g_w[12582912];          // all weights in fp16
__device__ __half g_xnh[BTOK * CDIM];     // layernorm output (fp16)
__device__ __half g_atth[BTOK * CDIM];    // attention output (fp16)
__device__ __half g_hh[BTOK * HID];       // gelu(fc1) output (fp16)
#define OQ  0
#define OP  3145728
#define OF1 4194304
#define OF2 8388608

// ---------------------------------------------------------------------------
// Helpers
// ---------------------------------------------------------------------------
static __device__ __forceinline__ uint32_t smem_u32(const void* p) {
    uint32_t a;
    asm("{ .reg .u64 t; cvta.to.shared.u64 t, %1; cvt.u32.u64 %0, t; }" : "=r"(a) : "l"(p));
    return a;
}
static __device__ __forceinline__ void cp16(uint32_t dst, const void* src) {
    asm volatile("cp.async.cg.shared.global [%0], [%1], 16;" :: "r"(dst), "l"(src));
}
#define CP_COMMIT() asm volatile("cp.async.commit_group;" ::: "memory")
#define CP_WAIT(n)  asm volatile("cp.async.wait_group %0;" :: "n"(n) : "memory")

#define LDMX4(r, addr) \
    asm volatile("ldmatrix.sync.aligned.m8n8.x4.shared.b16 {%0,%1,%2,%3}, [%4];" \
        : "=r"((r)[0]), "=r"((r)[1]), "=r"((r)[2]), "=r"((r)[3]) : "r"(addr))

#define MMA16816(d, a, b0, b1) \
    asm volatile("mma.sync.aligned.m16n8k16.row.col.f32.f16.f16.f32 " \
        "{%0,%1,%2,%3}, {%4,%5,%6,%7}, {%8,%9}, {%0,%1,%2,%3};" \
        : "+f"((d)[0]), "+f"((d)[1]), "+f"((d)[2]), "+f"((d)[3]) \
        : "r"((a)[0]), "r"((a)[1]), "r"((a)[2]), "r"((a)[3]), "r"(b0), "r"(b1))

// ---------------------------------------------------------------------------
// fp32 -> fp16 convert
// ---------------------------------------------------------------------------
__global__ __launch_bounds__(256)
void f2h_kernel(const float* __restrict__ x, __half* __restrict__ y, int n4) {
    int i = blockIdx.x * blockDim.x + threadIdx.x;
    if (i >= n4) return;
    float4 v = ((const float4*)x)[i];
    __half2 a = __floats2half2_rn(v.x, v.y);
    __half2 b = __floats2half2_rn(v.z, v.w);
    ((uint2*)y)[i] = make_uint2(*(uint32_t*)&a, *(uint32_t*)&b);
}

// ---------------------------------------------------------------------------
// LayerNorm: one row per block, 256 threads, outputs fp16
// ---------------------------------------------------------------------------
__global__ __launch_bounds__(256)
void ln_kernel(const float* __restrict__ x, const float* __restrict__ gg,
               const float* __restrict__ bb, __half* __restrict__ y) {
    __shared__ float red0[8], red1[8];
    __shared__ float s_mu, s_rs;
    int row = blockIdx.x;
    int tid = threadIdx.x;
    const float4* xr = (const float4*)(x + (size_t)row * CDIM);
    float4 v = xr[tid];
    float s  = v.x + v.y + v.z + v.w;
    float s2 = v.x * v.x + v.y * v.y + v.z * v.z + v.w * v.w;
    #pragma unroll
    for (int o = 16; o; o >>= 1) {
        s  += __shfl_xor_sync(0xFFFFFFFFu, s,  o);
        s2 += __shfl_xor_sync(0xFFFFFFFFu, s2, o);
    }
    if ((tid & 31) == 0) { red0[tid >> 5] = s; red1[tid >> 5] = s2; }
    __syncthreads();
    if (tid == 0) {
        float a = 0.f, b2 = 0.f;
        #pragma unroll
        for (int i = 0; i < 8; i++) { a += red0[i]; b2 += red1[i]; }
        float mu  = a * (1.0f / CDIM);
        float var = b2 * (1.0f / CDIM) - mu * mu;
        s_mu = mu;
        s_rs = rsqrtf(var + 1e-5f);
    }
    __syncthreads();
    float mu = s_mu, rs = s_rs;
    float4 gv = ((const float4*)gg)[tid];
    float4 bv = ((const float4*)bb)[tid];
    __half2 o0 = __floats2half2_rn((v.x - mu) * rs * gv.x + bv.x,
                                   (v.y - mu) * rs * gv.y + bv.y);
    __half2 o1 = __floats2half2_rn((v.z - mu) * rs * gv.z + bv.z,
                                   (v.w - mu) * rs * gv.w + bv.w);
    ((uint2*)(y + (size_t)row * CDIM))[tid] = make_uint2(*(uint32_t*)&o0, *(uint32_t*)&o1);
}

// ---------------------------------------------------------------------------
// HMMA GEMM: C[m,n] = A[m,:]·B[n,:] (both K-major fp16), fp32 accumulate.
// 128x128 CTA tile, BK=64, 3-stage cp.async pipeline, 8 warps (4m x 2n),
// warp tile 32x64 via m16n8k16.
// EPI: 0 plain fp32 out; 2 gelu(dot+bias) fp16 out; 3 res + dot + bias fp32 out
// ---------------------------------------------------------------------------
#define BK 64
#define NSTG 3
#define ATILE 16384                 // 128 rows * 128 bytes
#define STG_BYTES 32768
#define GEMM_SMEM (NSTG * STG_BYTES)

template <int EPI, typename OutT>
__global__ __launch_bounds__(256)
void gemm_mma(const __half* __restrict__ A, const __half* __restrict__ B,
              const float* __restrict__ bias, const float* __restrict__ res,
              OutT* __restrict__ C, int M, int N, int K) {
    extern __shared__ char smem[];
    uint32_t sb = smem_u32(smem);
    int tid = threadIdx.x, lane = tid & 31, wid = tid >> 5;
    int wm = wid & 3, wn = wid >> 2;
    int m0 = blockIdx.y * 128, n0 = blockIdx.x * 128;
    int nch = K >> 6;

    const __half* Ag = A + (size_t)m0 * K;
    const __half* Bg = B + (size_t)n0 * K;

    // per-thread load pattern: 4 chunks A + 4 chunks B per stage
    int lr[4], lsw[4];
    #pragma unroll
    for (int j = 0; j < 4; j++) {
        int c = tid + j * 256;
        lr[j] = c >> 3;
        uint32_t boff = (uint32_t)((c >> 3) * 128 + (c & 7) * 16);
        lsw[j] = boff ^ ((boff >> 3) & 0x70);
    }

    // prologue: stages 0..NSTG-2
    #pragma unroll
    for (int s = 0; s < NSTG - 1; s++) {
        uint32_t st = sb + s * STG_BYTES;
        int k0 = s * BK;
        #pragma unroll
        for (int j = 0; j < 4; j++) {
            int kc = (tid + j * 256) & 7;
            cp16(st + lsw[j],         Ag + (size_t)lr[j] * K + k0 + kc * 8);
            cp16(st + ATILE + lsw[j], Bg + (size_t)lr[j] * K + k0 + kc * 8);
        }
        CP_COMMIT();
    }

    float acc[2][8][4];
    #pragma unroll
    for (int mt = 0; mt < 2; mt++)
        #pragma unroll
        for (int j = 0; j < 8; j++)
            #pragma unroll
            for (int q = 0; q < 4; q++) acc[mt][j][q] = 0.f;

    // per-lane ldmatrix geometry
    int rA0 = wm * 32 + ((lane >> 3) & 1) * 8 + (lane & 7);  // + mt*16
    int kAo = (lane >> 4) << 4;                               // 0 or 16 bytes
    int rB0 = wn * 64 + (lane >> 4) * 8 + (lane & 7);         // + nb*16
    int kBo = ((lane >> 3) & 1) << 4;                         // 0 or 16 bytes

    for (int i = 0; i < nch; i++) {
        CP_WAIT(NSTG - 2);
        __syncthreads();
        if (i + NSTG - 1 < nch) {
            uint32_t st = sb + ((i + NSTG - 1) % NSTG) * STG_BYTES;
            int k0 = (i + NSTG - 1) * BK;
            #pragma unroll
            for (int j = 0; j < 4; j++) {
                int kc = (tid + j * 256) & 7;
                cp16(st + lsw[j],         Ag + (size_t)lr[j] * K + k0 + kc * 8);
                cp16(st + ATILE + lsw[j], Bg + (size_t)lr[j] * K + k0 + kc * 8);
            }
        }
        CP_COMMIT();

        uint32_t st = sb + (i % NSTG) * STG_BYTES;
        #pragma unroll
        for (int ks = 0; ks < 4; ks++) {
            uint32_t a[2][4], b[4][4];
            #pragma unroll
            for (int mt = 0; mt < 2; mt++) {
                int r = rA0 + mt * 16;
                int kb = ks * 32 + kAo;
                LDMX4(a[mt], st + r * 128 + (kb ^ ((r & 7) << 4)));
            }
            #pragma unroll
            for (int nb = 0; nb < 4; nb++) {
                int r = rB0 + nb * 16;
                int kb = ks * 32 + kBo;
                LDMX4(b[nb], st + ATILE + r * 128 + (kb ^ ((r & 7) << 4)));
            }
            #pragma unroll
            for (int mt = 0; mt < 2; mt++)
                #pragma unroll
                for (int j = 0; j < 8; j++)
                    MMA16816(acc[mt][j], a[mt], b[j >> 1][(j & 1) * 2], b[j >> 1][(j & 1) * 2 + 1]);
        }
    }

    // epilogue
    int rowb = m0 + wm * 32 + (lane >> 2);
    int colb = n0 + wn * 64 + (lane & 3) * 2;
    #pragma unroll
    for (int mt = 0; mt < 2; mt++) {
        #pragma unroll
        for (int j = 0; j < 8; j++) {
            int col = colb + j * 8;
            float bx = 0.f, by = 0.f;
            if (EPI >= 2) { float2 bv = __ldg((const float2*)&bias[col]); bx = bv.x; by = bv.y; }
            #pragma unroll
            for (int h = 0; h < 2; h++) {
                int row = rowb + mt * 16 + h * 8;
                float v0 = acc[mt][j][h * 2 + 0] + bx;
                float v1 = acc[mt][j][h * 2 + 1] + by;
                if (EPI == 2) {
                    v0 = 0.5f * v0 * (1.0f + erff(v0 * 0.70710678118654752f));
                    v1 = 0.5f * v1 * (1.0f + erff(v1 * 0.70710678118654752f));
                }
                if (EPI == 3) {
                    float2 rv = *(const float2*)&res[(size_t)row * N + col];
                    v0 += rv.x; v1 += rv.y;
                }
                if (sizeof(OutT) == 2) {
                    __half2 hv = __floats2half2_rn(v0, v1);
                    *(uint32_t*)&C[(size_t)row * N + col] = *(uint32_t*)&hv;
                } else {
                    *(float2*)&C[(size_t)row * N + col] = make_float2(v0, v1);
                }
            }
        }
    }
}

// ---------------------------------------------------------------------------
// Flash-style attention: one q row per thread, 64 q rows per block.
// Reads qkv fp32, writes attention output fp16.
// ---------------------------------------------------------------------------
__global__ __launch_bounds__(64)
void attn_kernel(const float* __restrict__ qkv, __half* __restrict__ out) {
    __shared__ float Ks[64][64];
    __shared__ float Vs[64][64];
    int tid = threadIdx.x;
    int bh = blockIdx.y;
    int b = bh >> 4;
    int h = bh & 15;
    int q0 = blockIdx.x * 64;

    size_t qbase = ((size_t)(b * NSEQ + q0 + tid)) * H3 + h * HD;
    float q[64];
    #pragma unroll
    for (int i = 0; i < 16; i++) {
        float4 v = *(const float4*)(qkv + qbase + i * 4);
        q[4 * i] = v.x; q[4 * i + 1] = v.y; q[4 * i + 2] = v.z; q[4 * i + 3] = v.w;
    }

    float m = -1e30f, l = 0.f;
    float acc[64];
    #pragma unroll
    for (int d = 0; d < 64; d++) acc[d] = 0.f;

    for (int kt = 0; kt < NSEQ; kt += 64) {
        __syncthreads();
        #pragma unroll
        for (int it = 0; it < 16; it++) {
            int idx = tid + it * 64;
            int r = idx >> 4, c4 = idx & 15;
            size_t kb = ((size_t)(b * NSEQ + kt + r)) * H3 + CDIM + h * HD;
            *(float4*)&Ks[r][c4 * 4] = *(const float4*)(qkv + kb + c4 * 4);
            *(float4*)&Vs[r][c4 * 4] = *(const float4*)(qkv + kb + CDIM + c4 * 4);
        }
        __syncthreads();
        #pragma unroll 2
        for (int j = 0; j < 64; j++) {
            float s = 0.f;
            #pragma unroll
            for (int d = 0; d < 64; d++) s += q[d] * Ks[j][d];
            s *= 0.125f;
            if (s > m) {
                float cs = __expf(m - s);
                l *= cs;
                #pragma unroll
                for (int d = 0; d < 64; d++) acc[d] *= cs;
                m = s;
            }
            float p = __expf(s - m);
            l += p;
            #pragma unroll
            for (int d = 0; d < 64; d++) acc[d] += p * Vs[j][d];
        }
    }

    float inv = 1.0f / l;
    size_t ob = ((size_t)(b * NSEQ + q0 + tid)) * CDIM + h * HD;
    #pragma unroll
    for (int i = 0; i < 16; i++) {
        __half2 h0 = __floats2half2_rn(acc[4 * i] * inv,     acc[4 * i + 1] * inv);
        __half2 h1 = __floats2half2_rn(acc[4 * i + 2] * inv, acc[4 * i + 3] * inv);
        *(uint2*)(out + ob + i * 4) = make_uint2(*(uint32_t*)&h0, *(uint32_t*)&h1);
    }
}

// ---------------------------------------------------------------------------
// Launch sequence
// ---------------------------------------------------------------------------
extern "C" void kernel_launch(void* const* d_in, const int* in_sizes, int n_in,
                              void* d_out, int out_size) {
    const float* x      = (const float*)d_in[0];
    const float* w_qkv  = (const float*)d_in[1];
    const float* w_proj = (const float*)d_in[2];
    const float* b_proj = (const float*)d_in[3];
    const float* ln1_g  = (const float*)d_in[4];
    const float* ln1_b  = (const float*)d_in[5];
    const float* ln2_g  = (const float*)d_in[6];
    const float* ln2_b  = (const float*)d_in[7];
    const float* w_fc1  = (const float*)d_in[8];
    const float* b_fc1  = (const float*)d_in[9];
    const float* w_fc2  = (const float*)d_in[10];
    const float* b_fc2  = (const float*)d_in[11];
    float* out = (float*)d_out;

    float* qkv;
    __half *w, *xnh, *atth, *hh;
    cudaGetSymbolAddress((void**)&qkv,  g_qkv);
    cudaGetSymbolAddress((void**)&w,    g_w);
    cudaGetSymbolAddress((void**)&xnh,  g_xnh);
    cudaGetSymbolAddress((void**)&atth, g_atth);
    cudaGetSymbolAddress((void**)&hh,   g_hh);

    cudaFuncSetAttribute(gemm_mma<0, float>,  cudaFuncAttributeMaxDynamicSharedMemorySize, GEMM_SMEM);
    cudaFuncSetAttribute(gemm_mma<2, __half>, cudaFuncAttributeMaxDynamicSharedMemorySize, GEMM_SMEM);
    cudaFuncSetAttribute(gemm_mma<3, float>,  cudaFuncAttributeMaxDynamicSharedMemorySize, GEMM_SMEM);

    // weight converts (fp32 -> fp16)
    f2h_kernel<<<(H3 * CDIM / 4 + 255) / 256, 256>>>(w_qkv,  w + OQ,  H3 * CDIM / 4);
    f2h_kernel<<<(CDIM * CDIM / 4 + 255) / 256, 256>>>(w_proj, w + OP,  CDIM * CDIM / 4);
    f2h_kernel<<<(HID * CDIM / 4 + 255) / 256, 256>>>(w_fc1,  w + OF1, HID * CDIM / 4);
    f2h_kernel<<<(CDIM * HID / 4 + 255) / 256, 256>>>(w_fc2,  w + OF2, CDIM * HID / 4);

    // 1. ln1(x) -> xnh (fp16)
    ln_kernel<<<BTOK, 256>>>(x, ln1_g, ln1_b, xnh);
    // 2. qkv = xnh @ w_qkv^T  (fp32 out)
    gemm_mma<0, float><<<dim3(H3 / 128, BTOK / 128), 256, GEMM_SMEM>>>(
        xnh, w + OQ, nullptr, nullptr, qkv, BTOK, H3, CDIM);
    // 3. attention -> atth (fp16)
    attn_kernel<<<dim3(NSEQ / 64, 2 * NHEAD), 64>>>(qkv, atth);
    // 4. x1 = x + atth @ w_proj^T + b_proj -> out
    gemm_mma<3, float><<<dim3(CDIM / 128, BTOK / 128), 256, GEMM_SMEM>>>(
        atth, w + OP, b_proj, x, out, BTOK, CDIM, CDIM);
    // 5. ln2(x1) -> xnh
    ln_kernel<<<BTOK, 256>>>(out, ln2_g, ln2_b, xnh);
    // 6. hh = gelu(xnh @ w_fc1^T + b_fc1)  (fp16 out)
    gemm_mma<2, __half><<<dim3(HID / 128, BTOK / 128), 256, GEMM_SMEM>>>(
        xnh, w + OF1, b_fc1, nullptr, hh, BTOK, HID, CDIM);
    // 7. out = x1 + hh @ w_fc2^T + b_fc2
    gemm_mma<3, float><<<dim3(CDIM / 128, BTOK / 128), 256, GEMM_SMEM>>>(
        hh, w + OF2, b_fc2, out, out, BTOK, CDIM, HID);
}